// round 1
// baseline (speedup 1.0000x reference)
#include <cuda_runtime.h>
#include <cuda_bf16.h>
#include <math.h>

// Problem constants (fixed shapes from reference):
// B=32, L=1024, C=1024, E=64, TASKS=8, K=2
#define B_ 32
#define L_ 1024
#define C_ 1024
#define E_ 64
#define T_ 8
#define Y_ELEMS (B_ * L_ * C_)   // 33554432

// Scratch (allocation-free rule: __device__ globals)
__device__ float d_s[B_ * L_];        // per (b,l) combined gate scale
__device__ int   d_e1[B_], d_e2[B_];  // top-2 expert indices per batch
__device__ float d_g1[B_], d_g2[B_];  // top-2 gate values per batch
__device__ float d_pm[B_ * E_];       // masked probs rows (for expert_mask)

// ---------------------------------------------------------------------------
// Kernel 1: gating. One block per batch.
//   hgate = gelu(x2 @ W1 + b1)   (exact erf gelu)
//   logits = (hgate @ W2)[:, :64]
//   probs = softmax(logits) + 1e-4
//   top-2, thresh, masked probs row
// ---------------------------------------------------------------------------
__global__ void gate_kernel(const float* __restrict__ x2,
                            const float* __restrict__ W1,
                            const float* __restrict__ b1,
                            const float* __restrict__ W2) {
    __shared__ float hg[C_];
    __shared__ float probs_sh[E_];
    __shared__ float thresh_sh;

    const int b = blockIdx.x;
    const int tid = threadIdx.x;

    // Load the 8 task features for this batch (L1-broadcast)
    float xr[T_];
#pragma unroll
    for (int t = 0; t < T_; t++) xr[t] = x2[b * T_ + t];

    // hgate: 1024 values, 4 per thread
#pragma unroll
    for (int j = 0; j < 4; j++) {
        int c = tid + j * 256;
        float h = b1[c];
#pragma unroll
        for (int t = 0; t < T_; t++) h = fmaf(xr[t], W1[t * C_ + c], h);
        // exact gelu: 0.5*x*(1+erf(x/sqrt(2)))
        h = 0.5f * h * (1.0f + erff(h * 0.70710678118654752f));
        hg[c] = h;
    }
    __syncthreads();

    // logits: threads 0..63 each compute one dot(hg, W2[:, e])
    if (tid < E_) {
        float acc = 0.0f;
        for (int c = 0; c < C_; c++)
            acc = fmaf(hg[c], W2[c * (2 * E_) + tid], acc);
        probs_sh[tid] = acc;  // temporarily logits
    }
    __syncthreads();

    // softmax + top-2 (tiny: single thread)
    if (tid == 0) {
        float m = -1e30f;
        for (int e = 0; e < E_; e++) m = fmaxf(m, probs_sh[e]);
        float s = 0.0f;
        for (int e = 0; e < E_; e++) {
            float p = expf(probs_sh[e] - m);
            probs_sh[e] = p;
            s += p;
        }
        float inv = 1.0f / s;
        float m1 = -1.0f, m2 = -1.0f;
        int i1 = 0, i2 = 0;
        for (int e = 0; e < E_; e++) {
            float p = probs_sh[e] * inv + 0.0001f;
            probs_sh[e] = p;
            if (p > m1)      { m2 = m1; i2 = i1; m1 = p; i1 = e; }
            else if (p > m2) { m2 = p; i2 = e; }
        }
        d_e1[b] = i1; d_e2[b] = i2;
        d_g1[b] = m1; d_g2[b] = m2;
        thresh_sh = m2;
    }
    __syncthreads();

    // masked probs row for expert_mask
    if (tid < E_) {
        float p = probs_sh[tid];
        d_pm[b * E_ + tid] = (p >= thresh_sh) ? p : 0.0f;
    }
}

// ---------------------------------------------------------------------------
// Kernel 2: finalize. One block, 1024 threads (one per l).
//   s[b,l] = g1*G[b,e1,l] + g2*G[b,e2,l]
//   token_mask[l] = sum_b (G[b,e1,l] + G[b,e2,l])
//   expert_mask[e] = sum_b pm[b,e]
// ---------------------------------------------------------------------------
__global__ void finalize_kernel(const float* __restrict__ G,
                                float* __restrict__ out) {
    __shared__ int   se1[B_], se2[B_];
    __shared__ float sg1[B_], sg2[B_];
    const int tid = threadIdx.x;

    if (tid < B_) {
        se1[tid] = d_e1[tid]; se2[tid] = d_e2[tid];
        sg1[tid] = d_g1[tid]; sg2[tid] = d_g2[tid];
    }
    __syncthreads();

    float tm = 0.0f;
#pragma unroll 4
    for (int b = 0; b < B_; b++) {
        float ga = G[((size_t)(b * E_ + se1[b])) * L_ + tid];
        float gb = G[((size_t)(b * E_ + se2[b])) * L_ + tid];
        d_s[b * L_ + tid] = fmaf(sg1[b], ga, sg2[b] * gb);
        tm += ga + gb;
    }
    // output layout: [y (32M), expert_mask (64), token_mask (1024)]
    out[Y_ELEMS + E_ + tid] = tm;

    if (tid < E_) {
        float em = 0.0f;
#pragma unroll
        for (int b = 0; b < B_; b++) em += d_pm[b * E_ + tid];
        out[Y_ELEMS + tid] = em;
    }
}

// ---------------------------------------------------------------------------
// Kernel 3: y = x * s  (bandwidth-bound, float4)
// ---------------------------------------------------------------------------
__global__ void scale_kernel(const float4* __restrict__ x,
                             float4* __restrict__ y) {
    const int N4 = Y_ELEMS / 4;  // 8388608; 256 float4 per (b,l) row
    int i = blockIdx.x * blockDim.x + threadIdx.x;
    const int stride = gridDim.x * blockDim.x;
    for (; i < N4; i += stride) {
        float s = d_s[i >> 8];
        float4 v = x[i];
        v.x *= s; v.y *= s; v.z *= s; v.w *= s;
        y[i] = v;
    }
}

// ---------------------------------------------------------------------------
extern "C" void kernel_launch(void* const* d_in, const int* in_sizes, int n_in,
                              void* d_out, int out_size) {
    const float* x  = (const float*)d_in[0];  // input_features (32,1024,1024)
    const float* x2 = (const float*)d_in[1];  // input_features2 (32,8)
    const float* G  = (const float*)d_in[2];  // G (32,64,1024)
    const float* W1 = (const float*)d_in[3];  // W1 (8,1024)
    const float* b1 = (const float*)d_in[4];  // b1 (1024,)
    const float* W2 = (const float*)d_in[5];  // W2 (1024,128)
    float* out = (float*)d_out;

    gate_kernel<<<B_, 256>>>(x2, W1, b1, W2);
    finalize_kernel<<<1, L_>>>(G, out);
    scale_kernel<<<8192, 256>>>((const float4*)x, (float4*)out);
}

// round 2
// speedup vs baseline: 1.7413x; 1.7413x over previous
#include <cuda_runtime.h>
#include <cuda_bf16.h>
#include <math.h>

// Problem constants (fixed shapes from reference):
// B=32, L=1024, C=1024, E=64, TASKS=8, K=2
#define B_ 32
#define L_ 1024
#define C_ 1024
#define E_ 64
#define T_ 8
#define Y_ELEMS (B_ * L_ * C_)   // 33554432

// Scratch (allocation-free rule: __device__ globals)
__device__ float d_s[B_ * L_];        // per (b,l) combined gate scale
__device__ float d_tm[B_ * L_];      // per-batch token-mask contribution
__device__ float d_pm[B_ * E_];       // masked probs rows (for expert_mask)

// ---------------------------------------------------------------------------
// Kernel 1: gating + per-batch scale row. One block of 1024 threads per batch.
//   hgate = gelu(x2 @ W1 + b1)   (exact erf gelu)
//   logits = (hgate @ W2)[:, :64]     (2-level parallel reduction)
//   probs = softmax(logits) + 1e-4, top-2, masked probs row
//   s[b,l] = g1*G[b,e1,l] + g2*G[b,e2,l];  tm[b,l] = G[b,e1,l]+G[b,e2,l]
// ---------------------------------------------------------------------------
__global__ __launch_bounds__(1024) void gate_kernel(
        const float* __restrict__ x2,
        const float* __restrict__ W1,
        const float* __restrict__ b1,
        const float* __restrict__ W2,
        const float* __restrict__ G) {
    __shared__ float hg[C_];
    __shared__ float partial[16 * E_];   // [chunk][expert]
    __shared__ float probs_sh[E_];
    __shared__ float thresh_sh;
    __shared__ int   se1, se2;
    __shared__ float sg1, sg2;

    const int b = blockIdx.x;
    const int tid = threadIdx.x;

    // --- hgate: one element per thread ---
    {
        float xr[T_];
#pragma unroll
        for (int t = 0; t < T_; t++) xr[t] = x2[b * T_ + t];
        float h = b1[tid];
#pragma unroll
        for (int t = 0; t < T_; t++) h = fmaf(xr[t], W1[t * C_ + tid], h);
        h = 0.5f * h * (1.0f + erff(h * 0.70710678118654752f));
        hg[tid] = h;
    }
    __syncthreads();

    // --- logits: thread t = (chunk ch = t>>6, expert e = t&63) ---
    {
        const int e  = tid & 63;
        const int ch = tid >> 6;         // 0..15
        const int c0 = ch * 64;
        float acc = 0.0f;
#pragma unroll 8
        for (int j = 0; j < 64; j++) {
            int c = c0 + j;
            acc = fmaf(hg[c], W2[c * (2 * E_) + e], acc);
        }
        partial[ch * E_ + e] = acc;
    }
    __syncthreads();

    if (tid < E_) {
        float acc = 0.0f;
#pragma unroll
        for (int ch = 0; ch < 16; ch++) acc += partial[ch * E_ + tid];
        probs_sh[tid] = acc;   // logits for now
    }
    __syncthreads();

    // --- softmax + top-2 (tiny; one thread, 64 elems) ---
    if (tid == 0) {
        float m = -1e30f;
#pragma unroll
        for (int e = 0; e < E_; e++) m = fmaxf(m, probs_sh[e]);
        float s = 0.0f;
#pragma unroll
        for (int e = 0; e < E_; e++) {
            float p = expf(probs_sh[e] - m);
            probs_sh[e] = p;
            s += p;
        }
        float inv = 1.0f / s;
        float m1 = -1.0f, m2 = -1.0f;
        int i1 = 0, i2 = 0;
#pragma unroll
        for (int e = 0; e < E_; e++) {
            float p = probs_sh[e] * inv + 0.0001f;
            probs_sh[e] = p;
            if (p > m1)      { m2 = m1; i2 = i1; m1 = p; i1 = e; }
            else if (p > m2) { m2 = p; i2 = e; }
        }
        se1 = i1; se2 = i2; sg1 = m1; sg2 = m2;
        thresh_sh = m2;
    }
    __syncthreads();

    // --- masked probs row for expert_mask ---
    if (tid < E_) {
        float p = probs_sh[tid];
        d_pm[b * E_ + tid] = (p >= thresh_sh) ? p : 0.0f;
    }

    // --- per-(b,l) scale + token-mask contribution (coalesced G reads) ---
    {
        float ga = G[((size_t)(b * E_ + se1)) * L_ + tid];
        float gb = G[((size_t)(b * E_ + se2)) * L_ + tid];
        d_s[b * L_ + tid]  = fmaf(sg1, ga, sg2 * gb);
        d_tm[b * L_ + tid] = ga + gb;
    }
}

// ---------------------------------------------------------------------------
// Kernel 2: masks. One block, 1024 threads (one per l).
//   token_mask[l] = sum_b tm[b,l];  expert_mask[e] = sum_b pm[b,e]
// ---------------------------------------------------------------------------
__global__ __launch_bounds__(1024) void mask_kernel(float* __restrict__ out) {
    const int tid = threadIdx.x;
    float tm = 0.0f;
#pragma unroll
    for (int b = 0; b < B_; b++) tm += d_tm[b * L_ + tid];
    // output layout: [y (32M), expert_mask (64), token_mask (1024)]
    out[Y_ELEMS + E_ + tid] = tm;

    if (tid < E_) {
        float em = 0.0f;
#pragma unroll
        for (int b = 0; b < B_; b++) em += d_pm[b * E_ + tid];
        out[Y_ELEMS + tid] = em;
    }
}

// ---------------------------------------------------------------------------
// Kernel 3: y = x * s  (bandwidth-bound). 4 rows per 256-thread block.
// Each row = 256 float4. Streaming hints: no reuse of x or y.
// ---------------------------------------------------------------------------
__global__ __launch_bounds__(256) void scale_kernel(
        const float4* __restrict__ x, float4* __restrict__ y) {
    const int row0 = blockIdx.x * 4;
    const int t = threadIdx.x;

    float s0 = d_s[row0 + 0];
    float s1 = d_s[row0 + 1];
    float s2 = d_s[row0 + 2];
    float s3 = d_s[row0 + 3];

    size_t i0 = (size_t)(row0 + 0) * 256 + t;
    size_t i1 = (size_t)(row0 + 1) * 256 + t;
    size_t i2 = (size_t)(row0 + 2) * 256 + t;
    size_t i3 = (size_t)(row0 + 3) * 256 + t;

    float4 v0 = __ldcs(&x[i0]);
    float4 v1 = __ldcs(&x[i1]);
    float4 v2 = __ldcs(&x[i2]);
    float4 v3 = __ldcs(&x[i3]);

    v0.x *= s0; v0.y *= s0; v0.z *= s0; v0.w *= s0;
    v1.x *= s1; v1.y *= s1; v1.z *= s1; v1.w *= s1;
    v2.x *= s2; v2.y *= s2; v2.z *= s2; v2.w *= s2;
    v3.x *= s3; v3.y *= s3; v3.z *= s3; v3.w *= s3;

    __stcs(&y[i0], v0);
    __stcs(&y[i1], v1);
    __stcs(&y[i2], v2);
    __stcs(&y[i3], v3);
}

// ---------------------------------------------------------------------------
extern "C" void kernel_launch(void* const* d_in, const int* in_sizes, int n_in,
                              void* d_out, int out_size) {
    const float* x  = (const float*)d_in[0];  // input_features (32,1024,1024)
    const float* x2 = (const float*)d_in[1];  // input_features2 (32,8)
    const float* G  = (const float*)d_in[2];  // G (32,64,1024)
    const float* W1 = (const float*)d_in[3];  // W1 (8,1024)
    const float* b1 = (const float*)d_in[4];  // b1 (1024,)
    const float* W2 = (const float*)d_in[5];  // W2 (1024,128)
    float* out = (float*)d_out;

    gate_kernel<<<B_, 1024>>>(x2, W1, b1, W2, G);
    mask_kernel<<<1, L_>>>(out);
    scale_kernel<<<(B_ * L_) / 4, 256>>>((const float4*)x, (float4*)out);
}